// round 2
// baseline (speedup 1.0000x reference)
#include <cuda_runtime.h>
#include <math.h>

#define BB 128
#define TT 384
#define CC 256
#define NH 4
#define NKV 2
#define HD 64
#define REP (NH / NKV)
#define M_ROWS (BB * TT)   // 49152

// Scratch (device globals -- no allocation allowed)
__device__ float g_q[(size_t)M_ROWS * (NH * HD)];   // [B,T,H,D]  50.3 MB
__device__ float g_k[(size_t)M_ROWS * (NKV * HD)];  // [B,T,KV,D] 25.2 MB
__device__ float g_v[(size_t)M_ROWS * (NKV * HD)];
__device__ float g_y[(size_t)M_ROWS * CC];          // attention output [B,T,C]

// ---------------------------------------------------------------------------
// Tiled SGEMM: C[M,N] = A[M,K] @ W[K,N].  BM=BN=64, BK=32, 256 threads,
// 4x4 outputs per thread.
// ---------------------------------------------------------------------------
__global__ void sgemm_kernel(const float* __restrict__ A,
                             const float* __restrict__ W,
                             float* __restrict__ Cout,
                             int M, int N, int K) {
    __shared__ float As[64][33];
    __shared__ float Bs[32][65];

    const int bx = blockIdx.x;          // N tile
    const int by = blockIdx.y;          // M tile
    const int tid = threadIdx.x;
    const int tx = tid & 15;            // 0..15
    const int ty = tid >> 4;            // 0..15

    float acc[4][4];
#pragma unroll
    for (int i = 0; i < 4; i++)
#pragma unroll
        for (int j = 0; j < 4; j++) acc[i][j] = 0.f;

    const float* Ab = A + (size_t)by * 64 * K;
    const float* Wb = W + bx * 64;

    for (int k0 = 0; k0 < K; k0 += 32) {
        // load A tile 64x32 (2048 elems / 256 thr = 8 each)
#pragma unroll
        for (int i = tid; i < 64 * 32; i += 256) {
            int r = i >> 5, c = i & 31;
            As[r][c] = Ab[(size_t)r * K + k0 + c];
        }
        // load W tile 32x64
#pragma unroll
        for (int i = tid; i < 32 * 64; i += 256) {
            int r = i >> 6, c = i & 63;
            Bs[r][c] = Wb[(size_t)(k0 + r) * N + c];
        }
        __syncthreads();

#pragma unroll
        for (int kk = 0; kk < 32; kk++) {
            float a[4], b[4];
#pragma unroll
            for (int i = 0; i < 4; i++) a[i] = As[ty * 4 + i][kk];
#pragma unroll
            for (int j = 0; j < 4; j++) b[j] = Bs[kk][tx * 4 + j];
#pragma unroll
            for (int i = 0; i < 4; i++)
#pragma unroll
                for (int j = 0; j < 4; j++) acc[i][j] += a[i] * b[j];
        }
        __syncthreads();
    }

#pragma unroll
    for (int i = 0; i < 4; i++) {
        int row = by * 64 + ty * 4 + i;
#pragma unroll
        for (int j = 0; j < 4; j++) {
            Cout[(size_t)row * N + bx * 64 + tx * 4 + j] = acc[i][j];
        }
    }
}

// ---------------------------------------------------------------------------
// RoPE, in place on g_q and g_k. One thread per rotation pair.
//   total pairs = M_ROWS * (NH + NKV) * 32
// ---------------------------------------------------------------------------
__global__ void rope_kernel() {
    const int total_q = M_ROWS * NH * 32;
    const int total   = M_ROWS * (NH + NKV) * 32;
    int idx = blockIdx.x * blockDim.x + threadIdx.x;
    if (idx >= total) return;

    float* buf;
    int row, head, p, nheads;
    if (idx < total_q) {
        buf = g_q; nheads = NH;
        p    = idx & 31;
        head = (idx >> 5) % NH;
        row  = idx / (32 * NH);
    } else {
        int id2 = idx - total_q;
        buf = g_k; nheads = NKV;
        p    = id2 & 31;
        head = (id2 >> 5) % NKV;
        row  = id2 / (32 * NKV);
    }
    int t = row % TT;

    // inv_freq = 10000^(-p/32)  -> exp2(-p * log2(10000)/32)
    const float kLog2_10000_over32 = 0.41524101186407246f;
    float inv = exp2f(-(float)p * kLog2_10000_over32);
    float ang = (float)t * inv;
    float c, s;
    sincosf(ang, &s, &c);

    size_t base = (size_t)row * (nheads * HD) + head * HD;
    float x1 = buf[base + p];
    float x2 = buf[base + p + 32];
    buf[base + p]      = x1 * c - x2 * s;
    buf[base + p + 32] = x2 * c + x1 * s;
}

// ---------------------------------------------------------------------------
// Flash-style causal GQA attention, fp32.
// grid = (T/128, H, B). block = 128 threads. Each thread owns one q row.
// K/V streamed through smem in 64-row tiles; streaming softmax in regs.
// ---------------------------------------------------------------------------
__global__ void __launch_bounds__(128) attn_kernel(const float* __restrict__ q,
                                                   const float* __restrict__ k,
                                                   const float* __restrict__ v,
                                                   float* __restrict__ y) {
    __shared__ float Ks[64][HD];   // 16 KB
    __shared__ float Vs[64][HD];   // 16 KB

    const int qb = blockIdx.x;              // 0..2
    const int h  = blockIdx.y;              // 0..3
    const int b  = blockIdx.z;              // 0..127
    const int g  = h / REP;                 // kv head
    const int tid = threadIdx.x;            // 0..127
    const int t = qb * 128 + tid;           // query position

    // load q row into registers, pre-scaled by 1/sqrt(D)
    float qreg[HD];
    {
        const float4* qrow =
            (const float4*)(q + (size_t)(b * TT + t) * (NH * HD) + h * HD);
#pragma unroll
        for (int i = 0; i < HD / 4; i++) {
            float4 f = qrow[i];
            qreg[4 * i + 0] = f.x * 0.125f;
            qreg[4 * i + 1] = f.y * 0.125f;
            qreg[4 * i + 2] = f.z * 0.125f;
            qreg[4 * i + 3] = f.w * 0.125f;
        }
    }

    float m = -1e30f, l = 0.f;
    float o[HD];
#pragma unroll
    for (int d = 0; d < HD; d++) o[d] = 0.f;

    const int ntiles = 2 * (qb + 1);        // key tiles of 64 covering [0, qb*128+128)
    for (int kt = 0; kt < ntiles; kt++) {
        const int kbase = kt * 64;
        __syncthreads();
        // cooperative load: 64 rows x 16 float4 = 1024 float4 / 128 thr = 8 each
#pragma unroll
        for (int i = tid; i < 64 * 16; i += 128) {
            int r = i >> 4, c4 = i & 15;
            size_t off = (size_t)(b * TT + kbase + r) * (NKV * HD) + g * HD + c4 * 4;
            ((float4*)&Ks[r][0])[c4] = *(const float4*)(k + off);
            ((float4*)&Vs[r][0])[c4] = *(const float4*)(v + off);
        }
        __syncthreads();

        int jend = t - kbase + 1;
        if (jend > 64) jend = 64;
        for (int jj = 0; jj < jend; jj++) {
            // s = q . K[jj]
            float s = 0.f;
            const float4* kr = (const float4*)&Ks[jj][0];
#pragma unroll
            for (int i = 0; i < HD / 4; i++) {
                float4 kk = kr[i];
                s += qreg[4 * i + 0] * kk.x + qreg[4 * i + 1] * kk.y +
                     qreg[4 * i + 2] * kk.z + qreg[4 * i + 3] * kk.w;
            }
            const float4* vr = (const float4*)&Vs[jj][0];
            if (s <= m) {
                float p = __expf(s - m);
                l += p;
#pragma unroll
                for (int i = 0; i < HD / 4; i++) {
                    float4 vv = vr[i];
                    o[4 * i + 0] += p * vv.x;
                    o[4 * i + 1] += p * vv.y;
                    o[4 * i + 2] += p * vv.z;
                    o[4 * i + 3] += p * vv.w;
                }
            } else {
                float corr = __expf(m - s);
                m = s;
                l = l * corr + 1.f;
#pragma unroll
                for (int i = 0; i < HD / 4; i++) {
                    float4 vv = vr[i];
                    o[4 * i + 0] = o[4 * i + 0] * corr + vv.x;
                    o[4 * i + 1] = o[4 * i + 1] * corr + vv.y;
                    o[4 * i + 2] = o[4 * i + 2] * corr + vv.z;
                    o[4 * i + 3] = o[4 * i + 3] * corr + vv.w;
                }
            }
        }
    }

    float invl = 1.f / l;
    float* yrow = y + (size_t)(b * TT + t) * CC + h * HD;
#pragma unroll
    for (int i = 0; i < HD / 4; i++) {
        float4 f;
        f.x = o[4 * i + 0] * invl;
        f.y = o[4 * i + 1] * invl;
        f.z = o[4 * i + 2] * invl;
        f.w = o[4 * i + 3] * invl;
        ((float4*)yrow)[i] = f;
    }
}

// ---------------------------------------------------------------------------
extern "C" void kernel_launch(void* const* d_in, const int* in_sizes, int n_in,
                              void* d_out, int out_size) {
    const float* x  = (const float*)d_in[0];   // [B,T,C]
    const float* Wq = (const float*)d_in[1];   // [C, H*D]
    const float* Wk = (const float*)d_in[2];   // [C, KV*D]
    const float* Wv = (const float*)d_in[3];   // [C, KV*D]
    const float* Wo = (const float*)d_in[4];   // [C, C]
    float* out = (float*)d_out;                // [B,T,C]

    float *q, *k, *v, *y;
    cudaGetSymbolAddress((void**)&q, g_q);
    cudaGetSymbolAddress((void**)&k, g_k);
    cudaGetSymbolAddress((void**)&v, g_v);
    cudaGetSymbolAddress((void**)&y, g_y);

    // QKV projections
    {
        dim3 gq((NH * HD) / 64, M_ROWS / 64);
        sgemm_kernel<<<gq, 256>>>(x, Wq, q, M_ROWS, NH * HD, CC);
        dim3 gkv((NKV * HD) / 64, M_ROWS / 64);
        sgemm_kernel<<<gkv, 256>>>(x, Wk, k, M_ROWS, NKV * HD, CC);
        sgemm_kernel<<<gkv, 256>>>(x, Wv, v, M_ROWS, NKV * HD, CC);
    }

    // RoPE on q and k
    {
        int total = M_ROWS * (NH + NKV) * 32;
        rope_kernel<<<(total + 255) / 256, 256>>>();
    }

    // Attention
    {
        dim3 ga(TT / 128, NH, BB);
        attn_kernel<<<ga, 128>>>(q, k, v, y);
    }

    // Output projection
    {
        dim3 go(CC / 64, M_ROWS / 64);
        sgemm_kernel<<<go, 256>>>(y, Wo, out, M_ROWS, CC, CC);
    }
}

// round 4
// speedup vs baseline: 2.0746x; 2.0746x over previous
#include <cuda_runtime.h>
#include <cstdint>
#include <math.h>

#define BB 128
#define TT 384
#define CC 256
#define NH 4
#define NKV 2
#define HD 64
#define REP (NH / NKV)
#define M_ROWS (BB * TT)   // 49152

// ---------------- scratch (device globals; allocation is forbidden) --------
__device__ float g_q[(size_t)M_ROWS * (NH * HD)];   // [B,T,H,D]
__device__ float g_k[(size_t)M_ROWS * (NKV * HD)];  // [B,T,KV,D]
__device__ float g_v[(size_t)M_ROWS * (NKV * HD)];
__device__ float g_y[(size_t)M_ROWS * CC];          // attention output [B,T,C]

// ---------------- helpers ---------------------------------------------------
__device__ __forceinline__ uint32_t smem_u32(const void* p) {
    uint32_t a;
    asm("{ .reg .u64 t; cvta.to.shared.u64 t, %1; cvt.u32.u64 %0, t; }"
        : "=r"(a) : "l"(p));
    return a;
}
__device__ __forceinline__ void cp16(uint32_t s, const void* g) {
    asm volatile("cp.async.cg.shared.global [%0], [%1], 16;" :: "r"(s), "l"(g));
}
__device__ __forceinline__ uint32_t f2tf32(float f) {
    uint32_t u;
    asm("cvt.rna.tf32.f32 %0, %1;" : "=r"(u) : "f"(f));
    return u;
}
__device__ __forceinline__ void mma_tf32(float* d, const uint32_t* a, const uint32_t* b) {
    asm volatile(
        "mma.sync.aligned.m16n8k8.row.col.f32.tf32.tf32.f32 "
        "{%0,%1,%2,%3}, {%4,%5,%6,%7}, {%8,%9}, {%0,%1,%2,%3};"
        : "+f"(d[0]), "+f"(d[1]), "+f"(d[2]), "+f"(d[3])
        : "r"(a[0]), "r"(a[1]), "r"(a[2]), "r"(a[3]), "r"(b[0]), "r"(b[1]));
}

// ---------------------------------------------------------------------------
// tf32 mma.sync GEMM: C[M,N] = A[M,K] @ W[K,N], K=256 fixed.
// CTA tile 128x128, BK=32, 8 warps of 64x32, 2-stage cp.async pipeline.
// Smem pads: A stride 36 floats, B stride 136 floats (both conflict-free for
// fragment LDS and 16B-aligned for cp.async).
// ---------------------------------------------------------------------------
#define GK 256
#define GBK 32
#define A_STRIDE 36
#define B_STRIDE 136
#define A_FLOATS (128 * A_STRIDE)                 // 4608
#define STAGE_FLOATS (A_FLOATS + GBK * B_STRIDE)  // 4608 + 4352 = 8960
#define GSMEM_BYTES (2 * STAGE_FLOATS * 4)        // 71680

__global__ void __launch_bounds__(256, 2)
gemm_mma_kernel(const float* __restrict__ A, const float* __restrict__ W,
                float* __restrict__ C, int N) {
    extern __shared__ float smem[];
    const uint32_t sbase = smem_u32(smem);

    const int tid  = threadIdx.x;
    const int warp = tid >> 5;
    const int lane = tid & 31;
    const int gid  = lane >> 2;     // 0..7
    const int tig  = lane & 3;      // 0..3
    const int warpM = (warp & 1) * 64;
    const int warpN = (warp >> 1) * 32;
    const int bx = blockIdx.x;      // N tile
    const int by = blockIdx.y;      // M tile

    const float* Abase = A + (size_t)by * 128 * GK;
    const float* Wbase = W + bx * 128;

    float acc[4][4][4];
#pragma unroll
    for (int mt = 0; mt < 4; mt++)
#pragma unroll
        for (int nt = 0; nt < 4; nt++)
#pragma unroll
            for (int r = 0; r < 4; r++) acc[mt][nt][r] = 0.f;

    // ---- stage loader ----
    auto load_stage = [&](int stage, int k0) {
        uint32_t sa = sbase + stage * (STAGE_FLOATS * 4);
        uint32_t sb = sa + A_FLOATS * 4;
        const float* Ag = Abase + k0;
        const float* Wg = Wbase + (size_t)k0 * N;
#pragma unroll
        for (int i = 0; i < 4; i++) {
            int id = tid + i * 256;            // 0..1023
            int m = id >> 3, c4 = id & 7;
            cp16(sa + (m * A_STRIDE + c4 * 4) * 4, Ag + (size_t)m * GK + c4 * 4);
        }
#pragma unroll
        for (int i = 0; i < 4; i++) {
            int id = tid + i * 256;
            int kk = id >> 5, c4 = id & 31;
            cp16(sb + (kk * B_STRIDE + c4 * 4) * 4, Wg + (size_t)kk * N + c4 * 4);
        }
        asm volatile("cp.async.commit_group;" ::: "memory");
    };

    auto compute_stage = [&](int stage) {
        const float* sa = smem + stage * STAGE_FLOATS;
        const float* sb = sa + A_FLOATS;
#pragma unroll
        for (int ks = 0; ks < 4; ks++) {
            const int kc = ks * 8;
            uint32_t bf[4][2];
#pragma unroll
            for (int nt = 0; nt < 4; nt++) {
                int col = warpN + nt * 8 + gid;
                bf[nt][0] = f2tf32(sb[(kc + tig) * B_STRIDE + col]);
                bf[nt][1] = f2tf32(sb[(kc + tig + 4) * B_STRIDE + col]);
            }
#pragma unroll
            for (int mt = 0; mt < 4; mt++) {
                int row = warpM + mt * 16 + gid;
                uint32_t af[4];
                af[0] = f2tf32(sa[row * A_STRIDE + kc + tig]);
                af[1] = f2tf32(sa[(row + 8) * A_STRIDE + kc + tig]);
                af[2] = f2tf32(sa[row * A_STRIDE + kc + tig + 4]);
                af[3] = f2tf32(sa[(row + 8) * A_STRIDE + kc + tig + 4]);
#pragma unroll
                for (int nt = 0; nt < 4; nt++) mma_tf32(acc[mt][nt], af, bf[nt]);
            }
        }
    };

    // ---- pipelined mainloop: 8 K-iterations of 32 ----
    load_stage(0, 0);
#pragma unroll
    for (int it = 0; it < 8; it++) {
        if (it + 1 < 8) {
            load_stage((it + 1) & 1, (it + 1) * GBK);
            asm volatile("cp.async.wait_group 1;" ::: "memory");
        } else {
            asm volatile("cp.async.wait_group 0;" ::: "memory");
        }
        __syncthreads();
        compute_stage(it & 1);
        __syncthreads();
    }

    // ---- epilogue ----
#pragma unroll
    for (int mt = 0; mt < 4; mt++) {
        int row = by * 128 + warpM + mt * 16 + gid;
#pragma unroll
        for (int nt = 0; nt < 4; nt++) {
            int col = bx * 128 + warpN + nt * 8 + tig * 2;
            *(float2*)(C + (size_t)row * N + col) =
                make_float2(acc[mt][nt][0], acc[mt][nt][1]);
            *(float2*)(C + (size_t)(row + 8) * N + col) =
                make_float2(acc[mt][nt][2], acc[mt][nt][3]);
        }
    }
}

// ---------------------------------------------------------------------------
// RoPE, in place on g_q and g_k. One thread per rotation pair.
// ---------------------------------------------------------------------------
__global__ void rope_kernel() {
    const int total_q = M_ROWS * NH * 32;
    const int total   = M_ROWS * (NH + NKV) * 32;
    int idx = blockIdx.x * blockDim.x + threadIdx.x;
    if (idx >= total) return;

    float* buf;
    int row, head, p, nheads;
    if (idx < total_q) {
        buf = g_q; nheads = NH;
        p    = idx & 31;
        head = (idx >> 5) & (NH - 1);
        row  = idx >> 7;
    } else {
        int id2 = idx - total_q;
        buf = g_k; nheads = NKV;
        p    = id2 & 31;
        head = (id2 >> 5) & (NKV - 1);
        row  = id2 >> 6;
    }
    int t = row % TT;

    const float kLog2_10000_over32 = 0.41524101186407246f;
    float inv = exp2f(-(float)p * kLog2_10000_over32);
    float ang = (float)t * inv;
    float c, s;
    sincosf(ang, &s, &c);

    size_t base = (size_t)row * (nheads * HD) + head * HD;
    float x1 = buf[base + p];
    float x2 = buf[base + p + 32];
    buf[base + p]      = x1 * c - x2 * s;
    buf[base + p + 32] = x2 * c + x1 * s;
}

// ---------------------------------------------------------------------------
// Flash-style causal GQA attention, fp32. One q row per thread.
// ---------------------------------------------------------------------------
__global__ void __launch_bounds__(128) attn_kernel(const float* __restrict__ q,
                                                   const float* __restrict__ k,
                                                   const float* __restrict__ v,
                                                   float* __restrict__ y) {
    __shared__ float Ks[64][HD];
    __shared__ float Vs[64][HD];

    const int qb = blockIdx.x;
    const int h  = blockIdx.y;
    const int b  = blockIdx.z;
    const int g  = h / REP;
    const int tid = threadIdx.x;
    const int t = qb * 128 + tid;

    float qreg[HD];
    {
        const float4* qrow =
            (const float4*)(q + (size_t)(b * TT + t) * (NH * HD) + h * HD);
#pragma unroll
        for (int i = 0; i < HD / 4; i++) {
            float4 f = qrow[i];
            qreg[4 * i + 0] = f.x * 0.125f;
            qreg[4 * i + 1] = f.y * 0.125f;
            qreg[4 * i + 2] = f.z * 0.125f;
            qreg[4 * i + 3] = f.w * 0.125f;
        }
    }

    float m = -1e30f, l = 0.f;
    float o[HD];
#pragma unroll
    for (int d = 0; d < HD; d++) o[d] = 0.f;

    const int ntiles = 2 * (qb + 1);
    for (int kt = 0; kt < ntiles; kt++) {
        const int kbase = kt * 64;
        __syncthreads();
#pragma unroll
        for (int i = tid; i < 64 * 16; i += 128) {
            int r = i >> 4, c4 = i & 15;
            size_t off = (size_t)(b * TT + kbase + r) * (NKV * HD) + g * HD + c4 * 4;
            ((float4*)&Ks[r][0])[c4] = *(const float4*)(k + off);
            ((float4*)&Vs[r][0])[c4] = *(const float4*)(v + off);
        }
        __syncthreads();

        int jend = t - kbase + 1;
        if (jend > 64) jend = 64;
        for (int jj = 0; jj < jend; jj++) {
            float s = 0.f;
            const float4* kr = (const float4*)&Ks[jj][0];
#pragma unroll
            for (int i = 0; i < HD / 4; i++) {
                float4 kk = kr[i];
                s += qreg[4 * i + 0] * kk.x + qreg[4 * i + 1] * kk.y +
                     qreg[4 * i + 2] * kk.z + qreg[4 * i + 3] * kk.w;
            }
            const float4* vr = (const float4*)&Vs[jj][0];
            if (s <= m) {
                float p = __expf(s - m);
                l += p;
#pragma unroll
                for (int i = 0; i < HD / 4; i++) {
                    float4 vv = vr[i];
                    o[4 * i + 0] += p * vv.x;
                    o[4 * i + 1] += p * vv.y;
                    o[4 * i + 2] += p * vv.z;
                    o[4 * i + 3] += p * vv.w;
                }
            } else {
                float corr = __expf(m - s);
                m = s;
                l = l * corr + 1.f;
#pragma unroll
                for (int i = 0; i < HD / 4; i++) {
                    float4 vv = vr[i];
                    o[4 * i + 0] = o[4 * i + 0] * corr + vv.x;
                    o[4 * i + 1] = o[4 * i + 1] * corr + vv.y;
                    o[4 * i + 2] = o[4 * i + 2] * corr + vv.z;
                    o[4 * i + 3] = o[4 * i + 3] * corr + vv.w;
                }
            }
        }
    }

    float invl = 1.f / l;
    float* yrow = y + (size_t)(b * TT + t) * CC + h * HD;
#pragma unroll
    for (int i = 0; i < HD / 4; i++) {
        float4 f;
        f.x = o[4 * i + 0] * invl;
        f.y = o[4 * i + 1] * invl;
        f.z = o[4 * i + 2] * invl;
        f.w = o[4 * i + 3] * invl;
        ((float4*)yrow)[i] = f;
    }
}

// ---------------------------------------------------------------------------
extern "C" void kernel_launch(void* const* d_in, const int* in_sizes, int n_in,
                              void* d_out, int out_size) {
    const float* x  = (const float*)d_in[0];
    const float* Wq = (const float*)d_in[1];
    const float* Wk = (const float*)d_in[2];
    const float* Wv = (const float*)d_in[3];
    const float* Wo = (const float*)d_in[4];
    float* out = (float*)d_out;

    float *q, *k, *v, *y;
    cudaGetSymbolAddress((void**)&q, g_q);
    cudaGetSymbolAddress((void**)&k, g_k);
    cudaGetSymbolAddress((void**)&v, g_v);
    cudaGetSymbolAddress((void**)&y, g_y);

    cudaFuncSetAttribute(gemm_mma_kernel,
                         cudaFuncAttributeMaxDynamicSharedMemorySize, GSMEM_BYTES);

    // QKV projections (tf32 tensor cores)
    gemm_mma_kernel<<<dim3((NH * HD) / 128, M_ROWS / 128), 256, GSMEM_BYTES>>>(
        x, Wq, q, NH * HD);
    gemm_mma_kernel<<<dim3((NKV * HD) / 128, M_ROWS / 128), 256, GSMEM_BYTES>>>(
        x, Wk, k, NKV * HD);
    gemm_mma_kernel<<<dim3((NKV * HD) / 128, M_ROWS / 128), 256, GSMEM_BYTES>>>(
        x, Wv, v, NKV * HD);

    // RoPE
    {
        int total = M_ROWS * (NH + NKV) * 32;
        rope_kernel<<<(total + 255) / 256, 256>>>();
    }

    // Attention
    {
        dim3 ga(TT / 128, NH, BB);
        attn_kernel<<<ga, 128>>>(q, k, v, y);
    }

    // Output projection
    gemm_mma_kernel<<<dim3(CC / 128, M_ROWS / 128), 256, GSMEM_BYTES>>>(
        y, Wo, out, CC);
}

// round 6
// speedup vs baseline: 4.4590x; 2.1493x over previous
#include <cuda_runtime.h>
#include <cstdint>
#include <math.h>

#define BB 128
#define TT 384
#define CC 256
#define NH 4
#define NKV 2
#define HD 64
#define M_ROWS (BB * TT)   // 49152

// ---------------- scratch (device globals; allocation is forbidden) --------
__device__ float g_qkv[(size_t)M_ROWS * 512];  // [B,T, q(256)|k(128)|v(128)]
__device__ float g_y[(size_t)M_ROWS * CC];     // attention output [B,T,C]

// ---------------- helpers ---------------------------------------------------
__device__ __forceinline__ uint32_t smem_u32(const void* p) {
    uint32_t a;
    asm("{ .reg .u64 t; cvta.to.shared.u64 t, %1; cvt.u32.u64 %0, t; }"
        : "=r"(a) : "l"(p));
    return a;
}
__device__ __forceinline__ void cp16(uint32_t s, const void* g) {
    asm volatile("cp.async.cg.shared.global [%0], [%1], 16;" :: "r"(s), "l"(g));
}
__device__ __forceinline__ uint32_t f2tf32(float f) {
    uint32_t u;
    asm("cvt.rna.tf32.f32 %0, %1;" : "=r"(u) : "f"(f));
    return u;
}
__device__ __forceinline__ void mma_tf32(float* d, const uint32_t* a, const uint32_t* b) {
    asm volatile(
        "mma.sync.aligned.m16n8k8.row.col.f32.tf32.tf32.f32 "
        "{%0,%1,%2,%3}, {%4,%5,%6,%7}, {%8,%9}, {%0,%1,%2,%3};"
        : "+f"(d[0]), "+f"(d[1]), "+f"(d[2]), "+f"(d[3])
        : "r"(a[0]), "r"(a[1]), "r"(a[2]), "r"(a[3]), "r"(b[0]), "r"(b[1]));
}

// ---------------------------------------------------------------------------
// Shared tf32 GEMM tile body: computes a 128x128 tile of A[128rows,K=256] @
// W[K=256, 128cols], A pre-offset to tile rows, W pre-offset to tile cols,
// Ct pre-offset to tile origin. 256 threads, BK=32, 2-stage cp.async.
// ---------------------------------------------------------------------------
#define GK 256
#define GBK 32
#define A_STRIDE 36
#define B_STRIDE 136
#define A_FLOATS (128 * A_STRIDE)                 // 4608
#define STAGE_FLOATS (A_FLOATS + GBK * B_STRIDE)  // 8960
#define GSMEM_BYTES (2 * STAGE_FLOATS * 4)        // 71680

__device__ __forceinline__ void gemm_tile_128(const float* __restrict__ A,
                                              const float* __restrict__ W,
                                              float* __restrict__ Ct,
                                              int ldW, int ldC) {
    extern __shared__ float smem[];
    const uint32_t sbase = smem_u32(smem);

    const int tid  = threadIdx.x;
    const int warp = tid >> 5;
    const int lane = tid & 31;
    const int gid  = lane >> 2;
    const int tig  = lane & 3;
    const int warpM = (warp & 1) * 64;
    const int warpN = (warp >> 1) * 32;

    float acc[4][4][4];
#pragma unroll
    for (int mt = 0; mt < 4; mt++)
#pragma unroll
        for (int nt = 0; nt < 4; nt++)
#pragma unroll
            for (int r = 0; r < 4; r++) acc[mt][nt][r] = 0.f;

    auto load_stage = [&](int stage, int k0) {
        uint32_t sa = sbase + stage * (STAGE_FLOATS * 4);
        uint32_t sb = sa + A_FLOATS * 4;
        const float* Ag = A + k0;
        const float* Wg = W + (size_t)k0 * ldW;
#pragma unroll
        for (int i = 0; i < 4; i++) {
            int id = tid + i * 256;
            int m = id >> 3, c4 = id & 7;
            cp16(sa + (m * A_STRIDE + c4 * 4) * 4, Ag + (size_t)m * GK + c4 * 4);
        }
#pragma unroll
        for (int i = 0; i < 4; i++) {
            int id = tid + i * 256;
            int kk = id >> 5, c4 = id & 31;
            cp16(sb + (kk * B_STRIDE + c4 * 4) * 4, Wg + (size_t)kk * ldW + c4 * 4);
        }
        asm volatile("cp.async.commit_group;" ::: "memory");
    };

    auto compute_stage = [&](int stage) {
        const float* sa = smem + stage * STAGE_FLOATS;
        const float* sb = sa + A_FLOATS;
#pragma unroll
        for (int ks = 0; ks < 4; ks++) {
            const int kc = ks * 8;
            uint32_t bf[4][2];
#pragma unroll
            for (int nt = 0; nt < 4; nt++) {
                int col = warpN + nt * 8 + gid;
                bf[nt][0] = f2tf32(sb[(kc + tig) * B_STRIDE + col]);
                bf[nt][1] = f2tf32(sb[(kc + tig + 4) * B_STRIDE + col]);
            }
#pragma unroll
            for (int mt = 0; mt < 4; mt++) {
                int row = warpM + mt * 16 + gid;
                uint32_t af[4];
                af[0] = f2tf32(sa[row * A_STRIDE + kc + tig]);
                af[1] = f2tf32(sa[(row + 8) * A_STRIDE + kc + tig]);
                af[2] = f2tf32(sa[row * A_STRIDE + kc + tig + 4]);
                af[3] = f2tf32(sa[(row + 8) * A_STRIDE + kc + tig + 4]);
#pragma unroll
                for (int nt = 0; nt < 4; nt++) mma_tf32(acc[mt][nt], af, bf[nt]);
            }
        }
    };

    load_stage(0, 0);
#pragma unroll
    for (int it = 0; it < 8; it++) {
        if (it + 1 < 8) {
            load_stage((it + 1) & 1, (it + 1) * GBK);
            asm volatile("cp.async.wait_group 1;" ::: "memory");
        } else {
            asm volatile("cp.async.wait_group 0;" ::: "memory");
        }
        __syncthreads();
        compute_stage(it & 1);
        __syncthreads();
    }

#pragma unroll
    for (int mt = 0; mt < 4; mt++) {
        int row = warpM + mt * 16 + gid;
#pragma unroll
        for (int nt = 0; nt < 4; nt++) {
            int col = warpN + nt * 8 + tig * 2;
            *(float2*)(Ct + (size_t)row * ldC + col) =
                make_float2(acc[mt][nt][0], acc[mt][nt][1]);
            *(float2*)(Ct + (size_t)(row + 8) * ldC + col) =
                make_float2(acc[mt][nt][2], acc[mt][nt][3]);
        }
    }
}

// Combined QKV projection: grid (4, M/128). bx selects Wq(0,1)/Wk(2)/Wv(3).
__global__ void __launch_bounds__(256, 2)
gemm_qkv_kernel(const float* __restrict__ x, const float* __restrict__ Wq,
                const float* __restrict__ Wk, const float* __restrict__ Wv,
                float* __restrict__ qkv) {
    const int bx = blockIdx.x, by = blockIdx.y;
    const float* W;
    int ldW;
    if (bx < 2)      { W = Wq + bx * 128; ldW = 256; }
    else if (bx == 2){ W = Wk;            ldW = 128; }
    else             { W = Wv;            ldW = 128; }
    gemm_tile_128(x + (size_t)by * 128 * GK, W,
                  qkv + (size_t)by * 128 * 512 + bx * 128, ldW, 512);
}

// Output projection: grid (2, M/128).
__global__ void __launch_bounds__(256, 2)
gemm_out_kernel(const float* __restrict__ y, const float* __restrict__ Wo,
                float* __restrict__ out) {
    const int bx = blockIdx.x, by = blockIdx.y;
    gemm_tile_128(y + (size_t)by * 128 * GK, Wo + bx * 128,
                  out + (size_t)by * 128 * 256 + bx * 128, 256, 256);
}

// ---------------------------------------------------------------------------
// RoPE in place on combined qkv. One thread per rotation pair.
// idx -> (row, h6 in 0..5, p in 0..31); h6<4 = q head, h6>=4 = k head.
// ---------------------------------------------------------------------------
__global__ void rope_kernel(float* __restrict__ qkv) {
    const int total = M_ROWS * 6 * 32;
    int idx = blockIdx.x * blockDim.x + threadIdx.x;
    if (idx >= total) return;
    int p   = idx & 31;
    int rem = idx >> 5;
    int h6  = rem % 6;
    int row = rem / 6;
    int col = (h6 < 4) ? h6 * 64 + p : 256 + (h6 - 4) * 64 + p;
    int t = row % TT;

    const float kLog2_10000_over32 = 0.41524101186407246f;
    float inv = exp2f(-(float)p * kLog2_10000_over32);
    float c, s;
    sincosf((float)t * inv, &s, &c);

    float* base = qkv + (size_t)row * 512 + col;
    float x1 = base[0];
    float x2 = base[32];
    base[0]  = x1 * c - x2 * s;
    base[32] = x2 * c + x1 * s;
}

// ---------------------------------------------------------------------------
// Tensor-core flash attention (tf32 mma). Grid (T/64, H, B), 128 threads.
// Warp w owns q rows w*16..w*16+15 of the 64-row q tile.
// Kt[d][key] (stride 72, conflict-free), Vs[key][d] (stride 72).
// ---------------------------------------------------------------------------
#define KSTR 72

__global__ void __launch_bounds__(128)
attn_mma_kernel(const float* __restrict__ qkv, float* __restrict__ y) {
    __shared__ uint32_t Kt[64 * KSTR];
    __shared__ uint32_t Vs[64 * KSTR];

    const int qb = blockIdx.x;       // q tile 0..5
    const int h  = blockIdx.y;
    const int b  = blockIdx.z;
    const int g  = h >> 1;           // kv head (REP=2)
    const int tid = threadIdx.x;
    const int w = tid >> 5;
    const int lane = tid & 31;
    const int gid = lane >> 2;
    const int tig = lane & 3;

    const float* qp = qkv + (size_t)(b * TT) * 512 + h * 64;
    const float* kp = qkv + (size_t)(b * TT) * 512 + 256 + g * 64;
    const float* vp = kp + 128;

    // ---- stage Q tile (scaled into exp2 domain) via Vs, extract A frags ----
    const float qscale = 0.18033688011112042f;  // 0.125 * log2(e)
    for (int i = tid; i < 1024; i += 128) {
        int r = i >> 4, c4 = i & 15;
        float4 f = *(const float4*)(qp + (size_t)(qb * 64 + r) * 512 + c4 * 4);
        uint32_t* d = &Vs[r * KSTR + c4 * 4];
        d[0] = __float_as_uint(f.x * qscale);
        d[1] = __float_as_uint(f.y * qscale);
        d[2] = __float_as_uint(f.z * qscale);
        d[3] = __float_as_uint(f.w * qscale);
    }
    __syncthreads();
    uint32_t aq[8][4];
    {
        int r0 = w * 16 + gid;
#pragma unroll
        for (int o = 0; o < 8; o++) {
            aq[o][0] = f2tf32(__uint_as_float(Vs[r0 * KSTR + o * 8 + tig]));
            aq[o][1] = f2tf32(__uint_as_float(Vs[(r0 + 8) * KSTR + o * 8 + tig]));
            aq[o][2] = f2tf32(__uint_as_float(Vs[r0 * KSTR + o * 8 + tig + 4]));
            aq[o][3] = f2tf32(__uint_as_float(Vs[(r0 + 8) * KSTR + o * 8 + tig + 4]));
        }
    }

    float m0 = -1e30f, m1 = -1e30f, l0 = 0.f, l1 = 0.f;
    float oacc[8][4];
#pragma unroll
    for (int nf = 0; nf < 8; nf++)
#pragma unroll
        for (int c = 0; c < 4; c++) oacc[nf][c] = 0.f;

    for (int kt = 0; kt <= qb; kt++) {
        const int kb = kt * 64;
        __syncthreads();   // everyone done reading previous tile
        // V: [key][d], tf32-converted, float4-coalesced
        for (int i = tid; i < 1024; i += 128) {
            int key = i >> 4, c4 = i & 15;
            float4 f = *(const float4*)(vp + (size_t)(kb + key) * 512 + c4 * 4);
            uint4 u;
            u.x = f2tf32(f.x); u.y = f2tf32(f.y);
            u.z = f2tf32(f.z); u.w = f2tf32(f.w);
            *(uint4*)&Vs[key * KSTR + c4 * 4] = u;
        }
        // K: transposed to [d][key]; lane->key mapping gives conflict-free STS
        for (int i = tid; i < 1024; i += 128) {
            int key = i & 63, c4 = i >> 6;
            float4 f = *(const float4*)(kp + (size_t)(kb + key) * 512 + c4 * 4);
            Kt[(c4 * 4 + 0) * KSTR + key] = f2tf32(f.x);
            Kt[(c4 * 4 + 1) * KSTR + key] = f2tf32(f.y);
            Kt[(c4 * 4 + 2) * KSTR + key] = f2tf32(f.z);
            Kt[(c4 * 4 + 3) * KSTR + key] = f2tf32(f.w);
        }
        __syncthreads();

        // ---- S = Q @ K^T ----
        float sacc[8][4];
#pragma unroll
        for (int nf = 0; nf < 8; nf++)
#pragma unroll
            for (int c = 0; c < 4; c++) sacc[nf][c] = 0.f;
#pragma unroll
        for (int nf = 0; nf < 8; nf++) {
#pragma unroll
            for (int o = 0; o < 8; o++) {
                uint32_t bk[2];
                bk[0] = Kt[(o * 8 + tig) * KSTR + nf * 8 + gid];
                bk[1] = Kt[(o * 8 + tig + 4) * KSTR + nf * 8 + gid];
                mma_tf32(sacc[nf], aq[o], bk);
            }
        }

        // ---- causal mask on diagonal tile ----
        if (kt == qb) {
            int jr0 = w * 16 + gid, jr1 = jr0 + 8;
#pragma unroll
            for (int nf = 0; nf < 8; nf++) {
                int jc = nf * 8 + 2 * tig;
                if (jc > jr0)     sacc[nf][0] = -1e30f;
                if (jc + 1 > jr0) sacc[nf][1] = -1e30f;
                if (jc > jr1)     sacc[nf][2] = -1e30f;
                if (jc + 1 > jr1) sacc[nf][3] = -1e30f;
            }
        }

        // ---- online softmax (exp2 domain) ----
        float rx0 = -1e30f, rx1 = -1e30f;
#pragma unroll
        for (int nf = 0; nf < 8; nf++) {
            rx0 = fmaxf(rx0, fmaxf(sacc[nf][0], sacc[nf][1]));
            rx1 = fmaxf(rx1, fmaxf(sacc[nf][2], sacc[nf][3]));
        }
        rx0 = fmaxf(rx0, __shfl_xor_sync(0xffffffffu, rx0, 1));
        rx0 = fmaxf(rx0, __shfl_xor_sync(0xffffffffu, rx0, 2));
        rx1 = fmaxf(rx1, __shfl_xor_sync(0xffffffffu, rx1, 1));
        rx1 = fmaxf(rx1, __shfl_xor_sync(0xffffffffu, rx1, 2));
        float mn0 = fmaxf(m0, rx0), mn1 = fmaxf(m1, rx1);
        float corr0 = exp2f(m0 - mn0), corr1 = exp2f(m1 - mn1);
        m0 = mn0; m1 = mn1;
        float rs0 = 0.f, rs1 = 0.f;
#pragma unroll
        for (int nf = 0; nf < 8; nf++) {
            sacc[nf][0] = exp2f(sacc[nf][0] - m0);
            sacc[nf][1] = exp2f(sacc[nf][1] - m0);
            sacc[nf][2] = exp2f(sacc[nf][2] - m1);
            sacc[nf][3] = exp2f(sacc[nf][3] - m1);
            rs0 += sacc[nf][0] + sacc[nf][1];
            rs1 += sacc[nf][2] + sacc[nf][3];
        }
        rs0 += __shfl_xor_sync(0xffffffffu, rs0, 1);
        rs0 += __shfl_xor_sync(0xffffffffu, rs0, 2);
        rs1 += __shfl_xor_sync(0xffffffffu, rs1, 1);
        rs1 += __shfl_xor_sync(0xffffffffu, rs1, 2);
        l0 = l0 * corr0 + rs0;
        l1 = l1 * corr1 + rs1;
#pragma unroll
        for (int nf = 0; nf < 8; nf++) {
            oacc[nf][0] *= corr0; oacc[nf][1] *= corr0;
            oacc[nf][2] *= corr1; oacc[nf][3] *= corr1;
        }

        // ---- O += P @ V  (P remapped C-layout -> A-layout via shuffles) ----
        const int srcA = (gid << 2) + (tig >> 1);
        const int srcB = srcA + 2;
        const bool odd = tig & 1;
#pragma unroll
        for (int ko = 0; ko < 8; ko++) {
            float s0a = __shfl_sync(0xffffffffu, sacc[ko][0], srcA);
            float s1a = __shfl_sync(0xffffffffu, sacc[ko][1], srcA);
            float s2a = __shfl_sync(0xffffffffu, sacc[ko][2], srcA);
            float s3a = __shfl_sync(0xffffffffu, sacc[ko][3], srcA);
            float s0b = __shfl_sync(0xffffffffu, sacc[ko][0], srcB);
            float s1b = __shfl_sync(0xffffffffu, sacc[ko][1], srcB);
            float s2b = __shfl_sync(0xffffffffu, sacc[ko][2], srcB);
            float s3b = __shfl_sync(0xffffffffu, sacc[ko][3], srcB);
            uint32_t pa[4];
            pa[0] = f2tf32(odd ? s1a : s0a);
            pa[1] = f2tf32(odd ? s3a : s2a);
            pa[2] = f2tf32(odd ? s1b : s0b);
            pa[3] = f2tf32(odd ? s3b : s2b);
#pragma unroll
            for (int nd = 0; nd < 8; nd++) {
                uint32_t bv[2];
                bv[0] = Vs[(ko * 8 + tig) * KSTR + nd * 8 + gid];
                bv[1] = Vs[(ko * 8 + tig + 4) * KSTR + nd * 8 + gid];
                mma_tf32(oacc[nd], pa, bv);
            }
        }
    }

    // ---- epilogue ----
    float il0 = 1.f / l0, il1 = 1.f / l1;
    float* y0 = y + (size_t)(b * TT + qb * 64 + w * 16 + gid) * 256 + h * 64;
    float* y1 = y0 + (size_t)8 * 256;
#pragma unroll
    for (int nf = 0; nf < 8; nf++) {
        *(float2*)(y0 + nf * 8 + 2 * tig) =
            make_float2(oacc[nf][0] * il0, oacc[nf][1] * il0);
        *(float2*)(y1 + nf * 8 + 2 * tig) =
            make_float2(oacc[nf][2] * il1, oacc[nf][3] * il1);
    }
}

// ---------------------------------------------------------------------------
extern "C" void kernel_launch(void* const* d_in, const int* in_sizes, int n_in,
                              void* d_out, int out_size) {
    const float* x  = (const float*)d_in[0];
    const float* Wq = (const float*)d_in[1];
    const float* Wk = (const float*)d_in[2];
    const float* Wv = (const float*)d_in[3];
    const float* Wo = (const float*)d_in[4];
    float* out = (float*)d_out;

    float *qkv, *y;
    cudaGetSymbolAddress((void**)&qkv, g_qkv);
    cudaGetSymbolAddress((void**)&y, g_y);

    cudaFuncSetAttribute(gemm_qkv_kernel,
                         cudaFuncAttributeMaxDynamicSharedMemorySize, GSMEM_BYTES);
    cudaFuncSetAttribute(gemm_out_kernel,
                         cudaFuncAttributeMaxDynamicSharedMemorySize, GSMEM_BYTES);

    // fused QKV projection -> qkv[M][512]
    gemm_qkv_kernel<<<dim3(4, M_ROWS / 128), 256, GSMEM_BYTES>>>(x, Wq, Wk, Wv, qkv);

    // RoPE on q|k regions of qkv
    {
        int total = M_ROWS * 6 * 32;
        rope_kernel<<<(total + 255) / 256, 256>>>(qkv);
    }

    // tensor-core flash attention -> y[M][256]
    {
        dim3 ga(TT / 64, NH, BB);
        attn_mma_kernel<<<ga, 128>>>(qkv, y);
    }

    // output projection
    gemm_out_kernel<<<dim3(2, M_ROWS / 128), 256, GSMEM_BYTES>>>(y, Wo, out);
}